// round 8
// baseline (speedup 1.0000x reference)
#include <cuda_runtime.h>
#include <math.h>

#define T_ 2048
#define H_ 2048
#define NH_ 16
#define NKV_ 4
#define DH_ 128
#define E_ 16
#define TOPK_ 2
#define I_ 1024
#define EPS_ 1e-6f

// ---------------- scratch ----------------
__device__ float g_cat[(size_t)T_ * 2 * H_];
__device__ float g_x[(size_t)T_ * H_];
__device__ float g_res[(size_t)T_ * H_];
__device__ float g_xn[(size_t)T_ * H_];
__device__ float g_qkv[(size_t)T_ * 3072];          // q[0:2048] k[2048:2560] v[2560:3072]
__device__ float g_attn[(size_t)T_ * NH_ * DH_];
__device__ float g_s[(size_t)NH_ * T_ * T_];        // attention scores / probs (256MB)
__device__ float g_gbuf[(size_t)T_ * TOPK_ * I_];
__device__ float g_ubuf[(size_t)T_ * TOPK_ * I_];
__device__ float g_downbuf[(size_t)T_ * TOPK_ * H_];
__device__ int   g_top_idx[T_ * TOPK_];
__device__ float g_top_w[T_ * TOPK_];
__device__ int   g_counts[E_];
__device__ int   g_counts2[E_];
__device__ int   g_offs[E_ + 1];
__device__ int   g_tok_of_slot[T_ * TOPK_];
__device__ float g_gate_of_slot[T_ * TOPK_];
__device__ int   g_slot_of_tok[T_ * TOPK_];

// ---------------- helpers ----------------
__device__ __forceinline__ float block_reduce_sum(float v) {
    __shared__ float sb[33];
    int tid = threadIdx.x;
#pragma unroll
    for (int o = 16; o > 0; o >>= 1) v += __shfl_xor_sync(0xffffffffu, v, o);
    if ((tid & 31) == 0) sb[tid >> 5] = v;
    __syncthreads();
    if (tid == 0) {
        float s = 0.f;
        int nw = (blockDim.x + 31) >> 5;
        for (int i = 0; i < nw; i++) s += sb[i];
        sb[32] = s;
    }
    __syncthreads();
    return sb[32];
}

__device__ __forceinline__ float block_reduce_max(float v) {
    __shared__ float sb[33];
    int tid = threadIdx.x;
#pragma unroll
    for (int o = 16; o > 0; o >>= 1) v = fmaxf(v, __shfl_xor_sync(0xffffffffu, v, o));
    if ((tid & 31) == 0) sb[tid >> 5] = v;
    __syncthreads();
    if (tid == 0) {
        float s = -1e30f;
        int nw = (blockDim.x + 31) >> 5;
        for (int i = 0; i < nw; i++) s = fmaxf(s, sb[i]);
        sb[32] = s;
    }
    __syncthreads();
    return sb[32];
}

// ---------------- fp32 SGEMM: 128x128 tile, 8x8 micro, double-buffered ----------------
__global__ __launch_bounds__(256, 2)
void gemm128(const float* __restrict__ A, const float* __restrict__ B,
             float* __restrict__ C,
             int M, int N, int Kd, int lda, int ldb, int ldc,
             const int* __restrict__ rowmap,
             const float* __restrict__ addsrc,
             float* __restrict__ Cdup,
             const int* __restrict__ segoff,
             long long strideB,
             const float* __restrict__ rowscale) {
    int row0 = 0, rowEnd = M;
    const float* Bp = B;
    if (segoff) {
        int e = blockIdx.z;
        row0 = segoff[e];
        rowEnd = segoff[e + 1];
        Bp = B + (long long)e * strideB;
    }
    int rbase = row0 + blockIdx.y * 128;
    if (rbase >= rowEnd) return;
    int cbase = blockIdx.x * 128;

    __shared__ float As[2][16][132];
    __shared__ float Bs[2][16][132];

    int tid = threadIdx.x;
    int tx = tid & 15, ty = tid >> 4;

    int am = tid & 127;
    int ak0 = (tid >> 7) * 8;
    int arow_g = rbase + am;
    const float* Arow = nullptr;
    if (arow_g < rowEnd) {
        int m = rowmap ? rowmap[arow_g] : arow_g;
        Arow = A + (long long)m * lda;
    }
    int br0 = tid >> 5;
    int bc4 = tid & 31;

    float acc[8][8];
#pragma unroll
    for (int i = 0; i < 8; i++)
#pragma unroll
        for (int j = 0; j < 8; j++) acc[i][j] = 0.f;

    float4 ra0, ra1, rb0, rb1;
    const float4 Z = make_float4(0.f, 0.f, 0.f, 0.f);

#define LOADG(K0)                                                                    \
    do {                                                                             \
        if (Arow) {                                                                  \
            ra0 = *(const float4*)(Arow + (K0) + ak0);                               \
            ra1 = *(const float4*)(Arow + (K0) + ak0 + 4);                           \
        } else { ra0 = Z; ra1 = Z; }                                                 \
        rb0 = *(const float4*)(Bp + (long long)((K0) + br0) * ldb + cbase + bc4 * 4);\
        rb1 = *(const float4*)(Bp + (long long)((K0) + br0 + 8) * ldb + cbase + bc4 * 4);\
    } while (0)

#define STOREB(BUF)                                                                  \
    do {                                                                             \
        As[BUF][ak0 + 0][am] = ra0.x; As[BUF][ak0 + 1][am] = ra0.y;                  \
        As[BUF][ak0 + 2][am] = ra0.z; As[BUF][ak0 + 3][am] = ra0.w;                  \
        As[BUF][ak0 + 4][am] = ra1.x; As[BUF][ak0 + 5][am] = ra1.y;                  \
        As[BUF][ak0 + 6][am] = ra1.z; As[BUF][ak0 + 7][am] = ra1.w;                  \
        *(float4*)&Bs[BUF][br0][bc4 * 4] = rb0;                                      \
        *(float4*)&Bs[BUF][br0 + 8][bc4 * 4] = rb1;                                  \
    } while (0)

    int nk = Kd >> 4;
    LOADG(0);
    STOREB(0);
    __syncthreads();
    for (int kt = 0; kt < nk; kt++) {
        int cur = kt & 1;
        if (kt + 1 < nk) LOADG((kt + 1) * 16);
#pragma unroll
        for (int kk = 0; kk < 16; kk++) {
            float a[8], b[8];
            float4 t;
            t = *(const float4*)&As[cur][kk][ty * 8];     a[0] = t.x; a[1] = t.y; a[2] = t.z; a[3] = t.w;
            t = *(const float4*)&As[cur][kk][ty * 8 + 4]; a[4] = t.x; a[5] = t.y; a[6] = t.z; a[7] = t.w;
            t = *(const float4*)&Bs[cur][kk][tx * 8];     b[0] = t.x; b[1] = t.y; b[2] = t.z; b[3] = t.w;
            t = *(const float4*)&Bs[cur][kk][tx * 8 + 4]; b[4] = t.x; b[5] = t.y; b[6] = t.z; b[7] = t.w;
#pragma unroll
            for (int i = 0; i < 8; i++)
#pragma unroll
                for (int j = 0; j < 8; j++) acc[i][j] += a[i] * b[j];
        }
        if (kt + 1 < nk) {
            STOREB(cur ^ 1);
            __syncthreads();
        }
    }
#undef LOADG
#undef STOREB

#pragma unroll
    for (int i = 0; i < 8; i++) {
        int r = rbase + ty * 8 + i;
        if (r >= rowEnd) break;
        float sc = rowscale ? rowscale[r] : 1.f;
        long long base = (long long)r * ldc + cbase + tx * 8;
        float4 v0 = make_float4(acc[i][0] * sc, acc[i][1] * sc, acc[i][2] * sc, acc[i][3] * sc);
        float4 v1 = make_float4(acc[i][4] * sc, acc[i][5] * sc, acc[i][6] * sc, acc[i][7] * sc);
        if (addsrc) {
            float4 s0 = *(const float4*)(addsrc + base);
            float4 s1 = *(const float4*)(addsrc + base + 4);
            v0.x += s0.x; v0.y += s0.y; v0.z += s0.z; v0.w += s0.w;
            v1.x += s1.x; v1.y += s1.y; v1.z += s1.z; v1.w += s1.w;
        }
        *(float4*)(C + base) = v0;
        *(float4*)(C + base + 4) = v1;
        if (Cdup) {
            *(float4*)(Cdup + base) = v0;
            *(float4*)(Cdup + base + 4) = v1;
        }
    }
}

// ---------------- fused QKV GEMM: C = g_qkv[T][3072] ----------------
__global__ __launch_bounds__(256, 2)
void gemm128_qkv(const float* __restrict__ A,
                 const float* __restrict__ wq, const float* __restrict__ wk,
                 const float* __restrict__ wv) {
    int x = blockIdx.x;
    const float* Bp;
    int ldb, bcol;
    if (x < 16)      { Bp = wq; ldb = 2048; bcol = x * 128; }
    else if (x < 20) { Bp = wk; ldb = 512;  bcol = (x - 16) * 128; }
    else             { Bp = wv; ldb = 512;  bcol = (x - 20) * 128; }
    int ccol = x * 128;
    int rbase = blockIdx.y * 128;

    __shared__ float As[2][16][132];
    __shared__ float Bs[2][16][132];

    int tid = threadIdx.x;
    int tx = tid & 15, ty = tid >> 4;
    int am = tid & 127;
    int ak0 = (tid >> 7) * 8;
    const float* Arow = A + (long long)(rbase + am) * H_;
    int br0 = tid >> 5;
    int bc4 = tid & 31;

    float acc[8][8];
#pragma unroll
    for (int i = 0; i < 8; i++)
#pragma unroll
        for (int j = 0; j < 8; j++) acc[i][j] = 0.f;

    float4 ra0, ra1, rb0, rb1;
#define LOADG(K0)                                                                    \
    do {                                                                             \
        ra0 = *(const float4*)(Arow + (K0) + ak0);                                   \
        ra1 = *(const float4*)(Arow + (K0) + ak0 + 4);                               \
        rb0 = *(const float4*)(Bp + (long long)((K0) + br0) * ldb + bcol + bc4 * 4); \
        rb1 = *(const float4*)(Bp + (long long)((K0) + br0 + 8) * ldb + bcol + bc4 * 4);\
    } while (0)
#define STOREB(BUF)                                                                  \
    do {                                                                             \
        As[BUF][ak0 + 0][am] = ra0.x; As[BUF][ak0 + 1][am] = ra0.y;                  \
        As[BUF][ak0 + 2][am] = ra0.z; As[BUF][ak0 + 3][am] = ra0.w;                  \
        As[BUF][ak0 + 4][am] = ra1.x; As[BUF][ak0 + 5][am] = ra1.y;                  \
        As[BUF][ak0 + 6][am] = ra1.z; As[BUF][ak0 + 7][am] = ra1.w;                  \
        *(float4*)&Bs[BUF][br0][bc4 * 4] = rb0;                                      \
        *(float4*)&Bs[BUF][br0 + 8][bc4 * 4] = rb1;                                  \
    } while (0)

    int nk = H_ >> 4;
    LOADG(0);
    STOREB(0);
    __syncthreads();
    for (int kt = 0; kt < nk; kt++) {
        int cur = kt & 1;
        if (kt + 1 < nk) LOADG((kt + 1) * 16);
#pragma unroll
        for (int kk = 0; kk < 16; kk++) {
            float a[8], b[8];
            float4 t;
            t = *(const float4*)&As[cur][kk][ty * 8];     a[0] = t.x; a[1] = t.y; a[2] = t.z; a[3] = t.w;
            t = *(const float4*)&As[cur][kk][ty * 8 + 4]; a[4] = t.x; a[5] = t.y; a[6] = t.z; a[7] = t.w;
            t = *(const float4*)&Bs[cur][kk][tx * 8];     b[0] = t.x; b[1] = t.y; b[2] = t.z; b[3] = t.w;
            t = *(const float4*)&Bs[cur][kk][tx * 8 + 4]; b[4] = t.x; b[5] = t.y; b[6] = t.z; b[7] = t.w;
#pragma unroll
            for (int i = 0; i < 8; i++)
#pragma unroll
                for (int j = 0; j < 8; j++) acc[i][j] += a[i] * b[j];
        }
        if (kt + 1 < nk) {
            STOREB(cur ^ 1);
            __syncthreads();
        }
    }
#undef LOADG
#undef STOREB
#pragma unroll
    for (int i = 0; i < 8; i++) {
        int r = rbase + ty * 8 + i;
        long long base = (long long)r * 3072 + ccol + tx * 8;
        *(float4*)(g_qkv + base) = make_float4(acc[i][0], acc[i][1], acc[i][2], acc[i][3]);
        *(float4*)(g_qkv + base + 4) = make_float4(acc[i][4], acc[i][5], acc[i][6], acc[i][7]);
    }
}

// ---------------- attention pass A: S = scale * Q @ K^T (causal tiles only) ----------------
__global__ __launch_bounds__(256, 2)
void gemm_qk() {
    int ktile = blockIdx.x, qtile = blockIdx.y, h = blockIdx.z;
    if (ktile > qtile) return;
    int qbase = qtile * 128, kbase = ktile * 128;
    int kvh = h >> 2;

    __shared__ float As[2][16][132];
    __shared__ float Bs[2][16][132];

    int tid = threadIdx.x;
    int tx = tid & 15, ty = tid >> 4;
    int am = tid & 127;
    int ak0 = (tid >> 7) * 8;
    const float* Arow = g_qkv + (size_t)(qbase + am) * 3072 + h * DH_;
    const float* Brow = g_qkv + (size_t)(kbase + am) * 3072 + 2048 + kvh * DH_;

    float acc[8][8];
#pragma unroll
    for (int i = 0; i < 8; i++)
#pragma unroll
        for (int j = 0; j < 8; j++) acc[i][j] = 0.f;

    float4 ra0, ra1, rb0, rb1;
#define LOADG(K0)                                                   \
    do {                                                            \
        ra0 = *(const float4*)(Arow + (K0) + ak0);                  \
        ra1 = *(const float4*)(Arow + (K0) + ak0 + 4);              \
        rb0 = *(const float4*)(Brow + (K0) + ak0);                  \
        rb1 = *(const float4*)(Brow + (K0) + ak0 + 4);              \
    } while (0)
#define STOREB(BUF)                                                                  \
    do {                                                                             \
        As[BUF][ak0 + 0][am] = ra0.x; As[BUF][ak0 + 1][am] = ra0.y;                  \
        As[BUF][ak0 + 2][am] = ra0.z; As[BUF][ak0 + 3][am] = ra0.w;                  \
        As[BUF][ak0 + 4][am] = ra1.x; As[BUF][ak0 + 5][am] = ra1.y;                  \
        As[BUF][ak0 + 6][am] = ra1.z; As[BUF][ak0 + 7][am] = ra1.w;                  \
        Bs[BUF][ak0 + 0][am] = rb0.x; Bs[BUF][ak0 + 1][am] = rb0.y;                  \
        Bs[BUF][ak0 + 2][am] = rb0.z; Bs[BUF][ak0 + 3][am] = rb0.w;                  \
        Bs[BUF][ak0 + 4][am] = rb1.x; Bs[BUF][ak0 + 5][am] = rb1.y;                  \
        Bs[BUF][ak0 + 6][am] = rb1.z; Bs[BUF][ak0 + 7][am] = rb1.w;                  \
    } while (0)

    const int nk = DH_ / 16;   // 8
    LOADG(0);
    STOREB(0);
    __syncthreads();
    for (int kt = 0; kt < nk; kt++) {
        int cur = kt & 1;
        if (kt + 1 < nk) LOADG((kt + 1) * 16);
#pragma unroll
        for (int kk = 0; kk < 16; kk++) {
            float a[8], b[8];
            float4 t;
            t = *(const float4*)&As[cur][kk][ty * 8];     a[0] = t.x; a[1] = t.y; a[2] = t.z; a[3] = t.w;
            t = *(const float4*)&As[cur][kk][ty * 8 + 4]; a[4] = t.x; a[5] = t.y; a[6] = t.z; a[7] = t.w;
            t = *(const float4*)&Bs[cur][kk][tx * 8];     b[0] = t.x; b[1] = t.y; b[2] = t.z; b[3] = t.w;
            t = *(const float4*)&Bs[cur][kk][tx * 8 + 4]; b[4] = t.x; b[5] = t.y; b[6] = t.z; b[7] = t.w;
#pragma unroll
            for (int i = 0; i < 8; i++)
#pragma unroll
                for (int j = 0; j < 8; j++) acc[i][j] += a[i] * b[j];
        }
        if (kt + 1 < nk) {
            STOREB(cur ^ 1);
            __syncthreads();
        }
    }
#undef LOADG
#undef STOREB

    const float scale = 0.08838834764831845f;
#pragma unroll
    for (int i = 0; i < 8; i++) {
        int q = qbase + ty * 8 + i;
        float* srow = g_s + ((size_t)h * T_ + q) * T_ + kbase + tx * 8;
        int k0 = kbase + tx * 8;
        float v[8];
#pragma unroll
        for (int j = 0; j < 8; j++)
            v[j] = (k0 + j <= q) ? acc[i][j] * scale : -1e30f;
        *(float4*)srow = make_float4(v[0], v[1], v[2], v[3]);
        *(float4*)(srow + 4) = make_float4(v[4], v[5], v[6], v[7]);
    }
}

// ---------------- attention pass B: row softmax (register-cached) ----------------
__global__ __launch_bounds__(256)
void softmax_rows() {
    int q = blockIdx.x, h = blockIdx.y;
    float* row = g_s + ((size_t)h * T_ + q) * T_;
    int L = q + 1;
    int pad_end = ((q >> 7) + 1) << 7;
    int tid = threadIdx.x;

    float v[8];
    int nchunk = (L + 255) >> 8;
    float mx = -1e30f;
#pragma unroll 4
    for (int c = 0; c < nchunk; c++) {
        int i = c * 256 + tid;
        v[c] = (i < L) ? row[i] : -1e30f;
        mx = fmaxf(mx, v[c]);
    }
    mx = block_reduce_max(mx);
    float s = 0.f;
#pragma unroll 4
    for (int c = 0; c < nchunk; c++) {
        v[c] = __expf(v[c] - mx);
        s += v[c];
    }
    float tot = block_reduce_sum(s);
    float inv = 1.f / tot;
#pragma unroll 4
    for (int c = 0; c < nchunk; c++) {
        int i = c * 256 + tid;
        if (i < L) row[i] = v[c] * inv;
    }
    for (int i = L + tid; i < pad_end; i += 256) row[i] = 0.f;
}

// ---------------- attention pass C: O = P @ V ----------------
__global__ __launch_bounds__(256, 2)
void gemm_pv() {
    int qt = (int)gridDim.x - 1 - (int)blockIdx.x;   // longest first
    int h = blockIdx.y;
    int rbase = qt * 128;
    int kvh = h >> 2;
    const float* Ap = g_s + (size_t)h * T_ * T_;
    const float* Bp = g_qkv + 2560 + kvh * DH_;      // V, row-stride 3072

    __shared__ float As[2][16][132];
    __shared__ float Bs[2][16][132];

    int tid = threadIdx.x;
    int tx = tid & 15, ty = tid >> 4;
    int am = tid & 127;
    int ak0 = (tid >> 7) * 8;
    const float* Arow = Ap + (size_t)(rbase + am) * T_;
    int br0 = tid >> 5;
    int bc4 = tid & 31;

    float acc[8][8];
#pragma unroll
    for (int i = 0; i < 8; i++)
#pragma unroll
        for (int j = 0; j < 8; j++) acc[i][j] = 0.f;

    float4 ra0, ra1, rb0, rb1;
#define LOADG(K0)                                                                    \
    do {                                                                             \
        ra0 = *(const float4*)(Arow + (K0) + ak0);                                   \
        ra1 = *(const float4*)(Arow + (K0) + ak0 + 4);                               \
        rb0 = *(const float4*)(Bp + (size_t)((K0) + br0) * 3072 + bc4 * 4);          \
        rb1 = *(const float4*)(Bp + (size_t)((K0) + br0 + 8) * 3072 + bc4 * 4);      \
    } while (0)
#define STOREB(BUF)                                                                  \
    do {                                                                             \
        As[BUF][ak0 + 0][am] = ra0.x; As[BUF][ak0 + 1][am] = ra0.y;                  \
        As[BUF][ak0 + 2][am] = ra0.z; As[BUF][ak0 + 3][am] = ra0.w;                  \
        As[BUF][ak0 + 4][am] = ra1.x; As[BUF][ak0 + 5][am] = ra1.y;                  \
        As[BUF][ak0 + 6][am] = ra1.z; As[BUF][ak0 + 7][am] = ra1.w;                  \
        *(float4*)&Bs[BUF][br0][bc4 * 4] = rb0;                                      \
        *(float4*)&Bs[BUF][br0 + 8][bc4 * 4] = rb1;                                  \
    } while (0)

    int nk = (qt + 1) * 8;   // K = (qt+1)*128
    LOADG(0);
    STOREB(0);
    __syncthreads();
    for (int kt = 0; kt < nk; kt++) {
        int cur = kt & 1;
        if (kt + 1 < nk) LOADG((kt + 1) * 16);
#pragma unroll
        for (int kk = 0; kk < 16; kk++) {
            float a[8], b[8];
            float4 t;
            t = *(const float4*)&As[cur][kk][ty * 8];     a[0] = t.x; a[1] = t.y; a[2] = t.z; a[3] = t.w;
            t = *(const float4*)&As[cur][kk][ty * 8 + 4]; a[4] = t.x; a[5] = t.y; a[6] = t.z; a[7] = t.w;
            t = *(const float4*)&Bs[cur][kk][tx * 8];     b[0] = t.x; b[1] = t.y; b[2] = t.z; b[3] = t.w;
            t = *(const float4*)&Bs[cur][kk][tx * 8 + 4]; b[4] = t.x; b[5] = t.y; b[6] = t.z; b[7] = t.w;
#pragma unroll
            for (int i = 0; i < 8; i++)
#pragma unroll
                for (int j = 0; j < 8; j++) acc[i][j] += a[i] * b[j];
        }
        if (kt + 1 < nk) {
            STOREB(cur ^ 1);
            __syncthreads();
        }
    }
#undef LOADG
#undef STOREB

#pragma unroll
    for (int i = 0; i < 8; i++) {
        int q = rbase + ty * 8 + i;
        float* dst = g_attn + (size_t)q * (NH_ * DH_) + h * DH_ + tx * 8;
        *(float4*)dst = make_float4(acc[i][0], acc[i][1], acc[i][2], acc[i][3]);
        *(float4*)(dst + 4) = make_float4(acc[i][4], acc[i][5], acc[i][6], acc[i][7]);
    }
}

// ---------------- embed lookup + rms -> concat ----------------
__global__ void embcat_kernel(const int* __restrict__ ids,
                              const float* __restrict__ emb_w,
                              const float* __restrict__ hid,
                              const float* __restrict__ we,
                              const float* __restrict__ wh) {
    int t = blockIdx.x;
    const float* er = emb_w + (size_t)ids[t] * H_;
    const float* hr = hid + (size_t)t * H_;
    float ss = 0.f;
    for (int h = threadIdx.x; h < H_; h += blockDim.x) { float v = er[h]; ss += v * v; }
    float tot = block_reduce_sum(ss);
    float rs = rsqrtf(tot / H_ + EPS_);
    for (int h = threadIdx.x; h < H_; h += blockDim.x)
        g_cat[(size_t)t * 2 * H_ + h] = er[h] * rs * (1.f + we[h]);
    ss = 0.f;
    for (int h = threadIdx.x; h < H_; h += blockDim.x) { float v = hr[h]; ss += v * v; }
    tot = block_reduce_sum(ss);
    rs = rsqrtf(tot / H_ + EPS_);
    for (int h = threadIdx.x; h < H_; h += blockDim.x)
        g_cat[(size_t)t * 2 * H_ + H_ + h] = hr[h] * rs * (1.f + wh[h]);
}

// ---------------- row RMS norm ----------------
__global__ void rmsnorm_kernel(const float* __restrict__ in,
                               const float* __restrict__ w,
                               float* __restrict__ out) {
    int t = blockIdx.x;
    const float* r = in + (size_t)t * H_;
    float ss = 0.f;
    for (int h = threadIdx.x; h < H_; h += blockDim.x) { float v = r[h]; ss += v * v; }
    float tot = block_reduce_sum(ss);
    float rs = rsqrtf(tot / H_ + EPS_);
    for (int h = threadIdx.x; h < H_; h += blockDim.x)
        out[(size_t)t * H_ + h] = r[h] * rs * (1.f + w[h]);
}

// ---------------- per-head rms + rope (in place on g_qkv) ----------------
__global__ void qkrope_kernel(int coloff, int nheads,
                              const float* __restrict__ nw,
                              const int* __restrict__ positions) {
    int t = blockIdx.x, h = blockIdx.y;
    float* v = g_qkv + (size_t)t * 3072 + coloff + h * DH_;
    int d = threadIdx.x;
    float val = v[d];
    float ss = val * val;
#pragma unroll
    for (int o = 16; o > 0; o >>= 1) ss += __shfl_xor_sync(0xffffffffu, ss, o);
    __shared__ float ws[4];
    if ((d & 31) == 0) ws[d >> 5] = ss;
    __syncthreads();
    float tot = ws[0] + ws[1] + ws[2] + ws[3];
    float rs = rsqrtf(tot / DH_ + EPS_);
    float n = val * rs * (1.f + nw[d]);
    __shared__ float nv[DH_];
    nv[d] = n;
    __syncthreads();
    int pos = positions[t];
    int i = d & 63;
    float inv = expf(-((float)i / 64.f) * 13.815510557964274f);
    float ang = (float)pos * inv;
    float c = cosf(ang), s = sinf(ang);
    float outv;
    if (d < 64) outv = nv[d] * c - nv[d + 64] * s;
    else        outv = nv[d] * c + nv[d - 64] * s;
    v[d] = outv;
}

// ---------------- router ----------------
__global__ void zero_counts_kernel() {
    if (threadIdx.x < E_) g_counts[threadIdx.x] = 0;
}

__global__ void router_kernel(const float* __restrict__ rw) {
    int t = blockIdx.x;
    __shared__ float part[256];
    __shared__ float logits[E_];
    int tid = threadIdx.x;
    int e = tid >> 4, c = tid & 15;
    float s = 0.f;
    const float* xr = g_xn + (size_t)t * H_;
    for (int h = c * 128; h < (c + 1) * 128; h++) s += xr[h] * rw[(size_t)h * E_ + e];
    part[tid] = s;
    __syncthreads();
    if (c == 0) {
        float tot = 0.f;
        for (int i = 0; i < 16; i++) tot += part[e * 16 + i];
        logits[e] = tot;
    }
    __syncthreads();
    if (tid == 0) {
        float mx = -1e30f;
        for (int i = 0; i < E_; i++) mx = fmaxf(mx, logits[i]);
        float p[E_];
        for (int i = 0; i < E_; i++) p[i] = expf(logits[i] - mx);
        int i0 = 0; float v0 = p[0];
        for (int i = 1; i < E_; i++) if (p[i] > v0) { v0 = p[i]; i0 = i; }
        int i1 = -1; float v1 = -1.f;
        for (int i = 0; i < E_; i++) if (i != i0 && p[i] > v1) { v1 = p[i]; i1 = i; }
        float denom = v0 + v1;
        g_top_idx[t * 2 + 0] = i0;
        g_top_idx[t * 2 + 1] = i1;
        g_top_w[t * 2 + 0] = v0 / denom;
        g_top_w[t * 2 + 1] = v1 / denom;
        atomicAdd(&g_counts[i0], 1);
        atomicAdd(&g_counts[i1], 1);
    }
}

__global__ void offsets_kernel() {
    if (threadIdx.x == 0) {
        int acc = 0;
        for (int e = 0; e < E_; e++) { g_offs[e] = acc; acc += g_counts[e]; }
        g_offs[E_] = acc;
    }
    if (threadIdx.x < E_) g_counts2[threadIdx.x] = 0;
}

__global__ void scatter_kernel() {
    int t = blockIdx.x * blockDim.x + threadIdx.x;
    if (t >= T_) return;
    for (int k = 0; k < TOPK_; k++) {
        int e = g_top_idx[t * 2 + k];
        int pos = atomicAdd(&g_counts2[e], 1);
        int slot = g_offs[e] + pos;
        g_tok_of_slot[slot] = t;
        g_gate_of_slot[slot] = g_top_w[t * 2 + k];
        g_slot_of_tok[t * 2 + k] = slot;
    }
}

// ---------------- silu(g)*u in place ----------------
__global__ void silu_mul_kernel() {
    size_t i = (size_t)blockIdx.x * blockDim.x + threadIdx.x;
    if (i >= (size_t)T_ * TOPK_ * I_) return;
    float x = g_gbuf[i];
    g_gbuf[i] = (x / (1.f + expf(-x))) * g_ubuf[i];
}

// ---------------- final combine + rms ----------------
__global__ void final_kernel(const float* __restrict__ fw, float* __restrict__ out) {
    int t = blockIdx.x;
    __shared__ float buf[H_];
    int s0 = g_slot_of_tok[t * 2 + 0];
    int s1 = g_slot_of_tok[t * 2 + 1];
    float ss = 0.f;
    for (int h = threadIdx.x; h < H_; h += blockDim.x) {
        float v = g_x[(size_t)t * H_ + h] + g_downbuf[(size_t)s0 * H_ + h] +
                  g_downbuf[(size_t)s1 * H_ + h];
        buf[h] = v;
        ss += v * v;
    }
    float tot = block_reduce_sum(ss);
    float rs = rsqrtf(tot / H_ + EPS_);
    for (int h = threadIdx.x; h < H_; h += blockDim.x)
        out[(size_t)t * H_ + h] = buf[h] * rs * (1.f + fw[h]);
}

// ---------------- launch ----------------
extern "C" void kernel_launch(void* const* d_in, const int* in_sizes, int n_in,
                              void* d_out, int out_size) {
    const int* input_ids      = (const int*)d_in[0];
    const int* positions      = (const int*)d_in[1];
    const float* hidden       = (const float*)d_in[2];
    const float* embed_w      = (const float*)d_in[4];
    const float* fc_w         = (const float*)d_in[5];
    const float* pre_fc_emb_w = (const float*)d_in[6];
    const float* pre_fc_hid_w = (const float*)d_in[7];
    const float* in_ln_w      = (const float*)d_in[8];
    const float* post_ln_w    = (const float*)d_in[9];
    const float* final_norm_w = (const float*)d_in[10];
    const float* wq           = (const float*)d_in[11];
    const float* wk           = (const float*)d_in[12];
    const float* wv           = (const float*)d_in[13];
    const float* wo           = (const float*)d_in[14];
    const float* q_norm_w     = (const float*)d_in[15];
    const float* k_norm_w     = (const float*)d_in[16];
    const float* router_w     = (const float*)d_in[17];
    const float* w_gate       = (const float*)d_in[18];
    const float* w_up         = (const float*)d_in[19];
    const float* w_down       = (const float*)d_in[20];
    float* out = (float*)d_out;

    float *p_cat, *p_x, *p_res, *p_xn, *p_attn, *p_g, *p_u, *p_down, *p_gate;
    int *p_tok, *p_offs;
    cudaGetSymbolAddress((void**)&p_cat, g_cat);
    cudaGetSymbolAddress((void**)&p_x, g_x);
    cudaGetSymbolAddress((void**)&p_res, g_res);
    cudaGetSymbolAddress((void**)&p_xn, g_xn);
    cudaGetSymbolAddress((void**)&p_attn, g_attn);
    cudaGetSymbolAddress((void**)&p_g, g_gbuf);
    cudaGetSymbolAddress((void**)&p_u, g_ubuf);
    cudaGetSymbolAddress((void**)&p_down, g_downbuf);
    cudaGetSymbolAddress((void**)&p_gate, g_gate_of_slot);
    cudaGetSymbolAddress((void**)&p_tok, g_tok_of_slot);
    cudaGetSymbolAddress((void**)&p_offs, g_offs);

    // 1. embed + rms -> concat
    embcat_kernel<<<T_, 256>>>(input_ids, embed_w, hidden, pre_fc_emb_w, pre_fc_hid_w);

    // 2. fc: x = cat @ fc_w ; residual = x
    gemm128<<<dim3(H_ / 128, T_ / 128), 256>>>(p_cat, fc_w, p_x, T_, H_, 2 * H_,
                                               2 * H_, H_, H_, nullptr, nullptr, p_res,
                                               nullptr, 0, nullptr);

    // 3. in_ln
    rmsnorm_kernel<<<T_, 256>>>(p_x, in_ln_w, p_xn);

    // 4. fused qkv -> g_qkv
    gemm128_qkv<<<dim3(24, T_ / 128), 256>>>(p_xn, wq, wk, wv);

    // 5. q/k norm + rope (in place on g_qkv)
    qkrope_kernel<<<dim3(T_, NH_), DH_>>>(0, NH_, q_norm_w, positions);
    qkrope_kernel<<<dim3(T_, NKV_), DH_>>>(2048, NKV_, k_norm_w, positions);

    // 6. attention: QK^T -> softmax -> PV
    gemm_qk<<<dim3(T_ / 128, T_ / 128, NH_), 256>>>();
    softmax_rows<<<dim3(T_, NH_), 256>>>();
    gemm_pv<<<dim3(T_ / 128, NH_), 256>>>();

    // 7. wo + residual -> x
    gemm128<<<dim3(H_ / 128, T_ / 128), 256>>>(p_attn, wo, p_x, T_, H_, NH_ * DH_,
                                               NH_ * DH_, H_, H_, nullptr, p_res, nullptr,
                                               nullptr, 0, nullptr);

    // 8. post_ln
    rmsnorm_kernel<<<T_, 256>>>(p_x, post_ln_w, p_xn);

    // 9. router + bucketing
    zero_counts_kernel<<<1, 32>>>();
    router_kernel<<<T_, 256>>>(router_w);
    offsets_kernel<<<1, 32>>>();
    scatter_kernel<<<(T_ + 255) / 256, 256>>>();

    // 10. MoE grouped GEMMs
    gemm128<<<dim3(I_ / 128, T_ / 128, E_), 256>>>(p_xn, w_gate, p_g, 0, I_, H_,
                                                   H_, I_, I_, p_tok, nullptr, nullptr,
                                                   p_offs, (long long)H_ * I_, nullptr);
    gemm128<<<dim3(I_ / 128, T_ / 128, E_), 256>>>(p_xn, w_up, p_u, 0, I_, H_,
                                                   H_, I_, I_, p_tok, nullptr, nullptr,
                                                   p_offs, (long long)H_ * I_, nullptr);
    silu_mul_kernel<<<((size_t)T_ * TOPK_ * I_ + 255) / 256, 256>>>();
    gemm128<<<dim3(H_ / 128, T_ / 128, E_), 256>>>(p_g, w_down, p_down, 0, H_, I_,
                                                   I_, H_, H_, nullptr, nullptr, nullptr,
                                                   p_offs, (long long)I_ * H_, p_gate);

    // 11. combine + final rms
    final_kernel<<<T_, 256>>>(final_norm_w, out);
}

// round 12
// speedup vs baseline: 1.3501x; 1.3501x over previous
#include <cuda_runtime.h>
#include <math.h>
#include <stdint.h>

#define T_ 2048
#define H_ 2048
#define NH_ 16
#define NKV_ 4
#define DH_ 128
#define E_ 16
#define TOPK_ 2
#define I_ 1024
#define EPS_ 1e-6f

// ---------------- scratch ----------------
__device__ float g_cat[(size_t)T_ * 2 * H_];
__device__ float g_x[(size_t)T_ * H_];
__device__ float g_res[(size_t)T_ * H_];
__device__ float g_xn[(size_t)T_ * H_];
__device__ float g_qkv[(size_t)T_ * 3072];
__device__ float g_attn[(size_t)T_ * NH_ * DH_];
__device__ float g_s[(size_t)NH_ * T_ * T_];
__device__ float g_gbuf[(size_t)T_ * TOPK_ * I_];
__device__ float g_ubuf[(size_t)T_ * TOPK_ * I_];
__device__ float g_downbuf[(size_t)T_ * TOPK_ * H_];
__device__ int   g_top_idx[T_ * TOPK_];
__device__ float g_top_w[T_ * TOPK_];
__device__ int   g_counts[E_];
__device__ int   g_counts2[E_];
__device__ int   g_offs[E_ + 1];
__device__ int   g_tok_of_slot[T_ * TOPK_];
__device__ float g_gate_of_slot[T_ * TOPK_];
__device__ int   g_slot_of_tok[T_ * TOPK_];

// ---------------- helpers ----------------
__device__ __forceinline__ float block_reduce_sum(float v) {
    __shared__ float sb[33];
    int tid = threadIdx.x;
#pragma unroll
    for (int o = 16; o > 0; o >>= 1) v += __shfl_xor_sync(0xffffffffu, v, o);
    if ((tid & 31) == 0) sb[tid >> 5] = v;
    __syncthreads();
    if (tid == 0) {
        float s = 0.f;
        int nw = (blockDim.x + 31) >> 5;
        for (int i = 0; i < nw; i++) s += sb[i];
        sb[32] = s;
    }
    __syncthreads();
    return sb[32];
}
__device__ __forceinline__ float block_reduce_max(float v) {
    __shared__ float sb[33];
    int tid = threadIdx.x;
#pragma unroll
    for (int o = 16; o > 0; o >>= 1) v = fmaxf(v, __shfl_xor_sync(0xffffffffu, v, o));
    if ((tid & 31) == 0) sb[tid >> 5] = v;
    __syncthreads();
    if (tid == 0) {
        float s = -1e30f;
        int nw = (blockDim.x + 31) >> 5;
        for (int i = 0; i < nw; i++) s = fmaxf(s, sb[i]);
        sb[32] = s;
    }
    __syncthreads();
    return sb[32];
}

__device__ __forceinline__ void t32split(float x, uint32_t& h, uint32_t& l) {
    uint32_t hb;
    asm("cvt.rna.tf32.f32 %0, %1;" : "=r"(hb) : "f"(x));
    float hf = __uint_as_float(hb);
    asm("cvt.rna.tf32.f32 %0, %1;" : "=r"(l) : "f"(x - hf));
    h = hb;
}
__device__ __forceinline__ void mma_tf32(float* d, const uint32_t* a, const uint32_t* b) {
    asm volatile("mma.sync.aligned.m16n8k8.row.col.f32.tf32.tf32.f32 "
                 "{%0,%1,%2,%3}, {%4,%5,%6,%7}, {%8,%9}, {%0,%1,%2,%3};"
                 : "+f"(d[0]), "+f"(d[1]), "+f"(d[2]), "+f"(d[3])
                 : "r"(a[0]), "r"(a[1]), "r"(a[2]), "r"(a[3]), "r"(b[0]), "r"(b[1]));
}

#define TP 136   // smem pitch (words); 136 % 32 = 8 -> all frag loads conflict-free

// ---------------- 3xTF32 tensor GEMM: 128x128 tile, 8 warps (4m x 2n) ----------------
#define T32_BODY(APTR_EXPR, BPTR_EXPR)                                               \
    __shared__ float As[2][16 * TP];                                                 \
    __shared__ float Bs[2][16 * TP];                                                 \
    int tid = threadIdx.x, lane = tid & 31, wid = tid >> 5;                          \
    int m0 = (wid & 3) * 32, n0 = (wid >> 2) * 64;                                   \
    int fr = lane >> 2, kc = lane & 3;                                               \
    int am = tid & 127, ak0 = (tid >> 7) * 8;                                        \
    const float* Arow = (APTR_EXPR);                                                 \
    const float* Brow_ = (BPTR_EXPR);                                                \
    int br0 = tid >> 5, bc4 = tid & 31;                                              \
    float acc[2][8][4];                                                              \
    _Pragma("unroll") for (int i = 0; i < 2; i++)                                    \
        _Pragma("unroll") for (int j = 0; j < 8; j++)                                \
            _Pragma("unroll") for (int c = 0; c < 4; c++) acc[i][j][c] = 0.f;        \
    float4 ra0, ra1, rb0, rb1;                                                       \
    const float4 Z4 = make_float4(0.f, 0.f, 0.f, 0.f);

#define T32_LOADG(K0)                                                                \
    do {                                                                             \
        if (Arow) {                                                                  \
            ra0 = *(const float4*)(Arow + (K0) + ak0);                               \
            ra1 = *(const float4*)(Arow + (K0) + ak0 + 4);                           \
        } else { ra0 = Z4; ra1 = Z4; }                                               \
        rb0 = *(const float4*)(Brow_ + (long long)((K0) + br0) * ldb + bc4 * 4);     \
        rb1 = *(const float4*)(Brow_ + (long long)((K0) + br0 + 8) * ldb + bc4 * 4); \
    } while (0)

#define T32_STOREB(BUF)                                                              \
    do {                                                                             \
        As[BUF][(ak0 + 0) * TP + am] = ra0.x;                                        \
        As[BUF][(ak0 + 1) * TP + am] = ra0.y;                                        \
        As[BUF][(ak0 + 2) * TP + am] = ra0.z;                                        \
        As[BUF][(ak0 + 3) * TP + am] = ra0.w;                                        \
        As[BUF][(ak0 + 4) * TP + am] = ra1.x;                                        \
        As[BUF][(ak0 + 5) * TP + am] = ra1.y;                                        \
        As[BUF][(ak0 + 6) * TP + am] = ra1.z;                                        \
        As[BUF][(ak0 + 7) * TP + am] = ra1.w;                                        \
        *(float4*)&Bs[BUF][br0 * TP + bc4 * 4] = rb0;                                \
        *(float4*)&Bs[BUF][(br0 + 8) * TP + bc4 * 4] = rb1;                          \
    } while (0)

#define T32_COMPUTE(CUR)                                                             \
    _Pragma("unroll")                                                                \
    for (int s = 0; s < 2; s++) {                                                    \
        const float* Ab  = &As[CUR][(s * 8 + kc) * TP];                              \
        const float* Ab4 = &As[CUR][(s * 8 + kc + 4) * TP];                          \
        const float* Bb  = &Bs[CUR][(s * 8 + kc) * TP];                              \
        const float* Bb4 = &Bs[CUR][(s * 8 + kc + 4) * TP];                          \
        uint32_t ah[2][4], al[2][4], bh[8][2], bl[8][2];                             \
        _Pragma("unroll")                                                            \
        for (int mt = 0; mt < 2; mt++) {                                             \
            int mm = m0 + mt * 16 + fr;                                              \
            t32split(Ab[mm],      ah[mt][0], al[mt][0]);                             \
            t32split(Ab[mm + 8],  ah[mt][1], al[mt][1]);                             \
            t32split(Ab4[mm],     ah[mt][2], al[mt][2]);                             \
            t32split(Ab4[mm + 8], ah[mt][3], al[mt][3]);                             \
        }                                                                            \
        _Pragma("unroll")                                                            \
        for (int nt = 0; nt < 8; nt++) {                                             \
            int nn = n0 + nt * 8 + fr;                                               \
            t32split(Bb[nn],  bh[nt][0], bl[nt][0]);                                 \
            t32split(Bb4[nn], bh[nt][1], bl[nt][1]);                                 \
        }                                                                            \
        _Pragma("unroll")                                                            \
        for (int mt = 0; mt < 2; mt++)                                               \
            _Pragma("unroll")                                                        \
            for (int nt = 0; nt < 8; nt++) {                                         \
                mma_tf32(acc[mt][nt], ah[mt], bh[nt]);                               \
                mma_tf32(acc[mt][nt], ah[mt], bl[nt]);                               \
                mma_tf32(acc[mt][nt], al[mt], bh[nt]);                               \
            }                                                                        \
    }

__global__ __launch_bounds__(256, 2)
void gemm_t32(const float* __restrict__ A, const float* __restrict__ B,
              float* __restrict__ C,
              int M, int Kd, int lda, int ldb, int ldc,
              const int* __restrict__ rowmap,
              const float* __restrict__ addsrc, float* __restrict__ Cdup,
              const int* __restrict__ segoff, long long strideB,
              const float* __restrict__ rowscale) {
    int row0 = 0, rowEnd = M;
    const float* Bp = B;
    if (segoff) {
        int e = blockIdx.z;
        row0 = segoff[e];
        rowEnd = segoff[e + 1];
        Bp = B + (long long)e * strideB;
    }
    int rbase = row0 + blockIdx.y * 128;
    if (rbase >= rowEnd) return;
    int cbase = blockIdx.x * 128;

    T32_BODY(
        (rbase + (threadIdx.x & 127) < rowEnd)
            ? A + (long long)(rowmap ? rowmap[rbase + (threadIdx.x & 127)]
                                     : rbase + (threadIdx.x & 127)) * lda
            : (const float*)nullptr,
        Bp + cbase);

    int nk = Kd >> 4;
    T32_LOADG(0);
    T32_STOREB(0);
    __syncthreads();
    for (int kt = 0; kt < nk; kt++) {
        int cur = kt & 1;
        if (kt + 1 < nk) T32_LOADG((kt + 1) * 16);
        T32_COMPUTE(cur);
        if (kt + 1 < nk) {
            T32_STOREB(cur ^ 1);
            __syncthreads();
        }
    }

#pragma unroll
    for (int mt = 0; mt < 2; mt++)
#pragma unroll
        for (int half = 0; half < 2; half++) {
            int row = rbase + m0 + mt * 16 + fr + half * 8;
            if (row >= rowEnd) continue;
            float sc = rowscale ? rowscale[row] : 1.f;
            long long base = (long long)row * ldc + cbase + n0 + 2 * kc;
#pragma unroll
            for (int nt = 0; nt < 8; nt++) {
                long long o = base + nt * 8;
                float2 v = make_float2(acc[mt][nt][half * 2 + 0] * sc,
                                       acc[mt][nt][half * 2 + 1] * sc);
                if (addsrc) {
                    float2 s = *(const float2*)(addsrc + o);
                    v.x += s.x; v.y += s.y;
                }
                *(float2*)(C + o) = v;
                if (Cdup) *(float2*)(Cdup + o) = v;
            }
        }
}

// fused QKV variant -> g_qkv[T][3072]
__global__ __launch_bounds__(256, 2)
void gemm_t32_qkv(const float* __restrict__ A,
                  const float* __restrict__ wq, const float* __restrict__ wk,
                  const float* __restrict__ wv) {
    int x = blockIdx.x;
    const float* Bsel;
    int ldb, bcol;
    if (x < 16)      { Bsel = wq; ldb = 2048; bcol = x * 128; }
    else if (x < 20) { Bsel = wk; ldb = 512;  bcol = (x - 16) * 128; }
    else             { Bsel = wv; ldb = 512;  bcol = (x - 20) * 128; }
    int ccol = x * 128;
    int rbase = blockIdx.y * 128;

    T32_BODY(A + (long long)(rbase + (threadIdx.x & 127)) * H_, Bsel + bcol);

    int nk = H_ >> 4;
    T32_LOADG(0);
    T32_STOREB(0);
    __syncthreads();
    for (int kt = 0; kt < nk; kt++) {
        int cur = kt & 1;
        if (kt + 1 < nk) T32_LOADG((kt + 1) * 16);
        T32_COMPUTE(cur);
        if (kt + 1 < nk) {
            T32_STOREB(cur ^ 1);
            __syncthreads();
        }
    }

#pragma unroll
    for (int mt = 0; mt < 2; mt++)
#pragma unroll
        for (int half = 0; half < 2; half++) {
            int row = rbase + m0 + mt * 16 + fr + half * 8;
            long long base = (long long)row * 3072 + ccol + n0 + 2 * kc;
#pragma unroll
            for (int nt = 0; nt < 8; nt++)
                *(float2*)(g_qkv + base + nt * 8) =
                    make_float2(acc[mt][nt][half * 2 + 0], acc[mt][nt][half * 2 + 1]);
        }
}

// ---------------- attention pass A: S = scale*Q@K^T (fp32, causal tiles) ----------------
__global__ __launch_bounds__(256, 2)
void gemm_qk() {
    int ktile = blockIdx.x, qtile = blockIdx.y, h = blockIdx.z;
    if (ktile > qtile) return;
    int qbase = qtile * 128, kbase = ktile * 128, kvh = h >> 2;
    __shared__ float As[2][16][132];
    __shared__ float Bs[2][16][132];
    int tid = threadIdx.x, tx = tid & 15, ty = tid >> 4;
    int am = tid & 127, ak0 = (tid >> 7) * 8;
    const float* Arow = g_qkv + (size_t)(qbase + am) * 3072 + h * DH_;
    const float* Brow = g_qkv + (size_t)(kbase + am) * 3072 + 2048 + kvh * DH_;
    float acc[8][8];
#pragma unroll
    for (int i = 0; i < 8; i++)
#pragma unroll
        for (int j = 0; j < 8; j++) acc[i][j] = 0.f;
    float4 ra0, ra1, rb0, rb1;
#define LOADG(K0) do { ra0 = *(const float4*)(Arow + (K0) + ak0);                    \
        ra1 = *(const float4*)(Arow + (K0) + ak0 + 4);                               \
        rb0 = *(const float4*)(Brow + (K0) + ak0);                                   \
        rb1 = *(const float4*)(Brow + (K0) + ak0 + 4); } while (0)
#define STOREB(BUF) do {                                                             \
        As[BUF][ak0 + 0][am] = ra0.x; As[BUF][ak0 + 1][am] = ra0.y;                  \
        As[BUF][ak0 + 2][am] = ra0.z; As[BUF][ak0 + 3][am] = ra0.w;                  \
        As[BUF][ak0 + 4][am] = ra1.x; As[BUF][ak0 + 5][am] = ra1.y;                  \
        As[BUF][ak0 + 6][am] = ra1.z; As[BUF][ak0 + 7][am] = ra1.w;                  \
        Bs[BUF][ak0 + 0][am] = rb0.x; Bs[BUF][ak0 + 1][am] = rb0.y;                  \
        Bs[BUF][ak0 + 2][am] = rb0.z; Bs[BUF][ak0 + 3][am] = rb0.w;                  \
        Bs[BUF][ak0 + 4][am] = rb1.x; Bs[BUF][ak0 + 5][am] = rb1.y;                  \
        Bs[BUF][ak0 + 6][am] = rb1.z; Bs[BUF][ak0 + 7][am] = rb1.w; } while (0)
    const int nk = 8;
    LOADG(0); STOREB(0); __syncthreads();
    for (int kt = 0; kt < nk; kt++) {
        int cur = kt & 1;
        if (kt + 1 < nk) LOADG((kt + 1) * 16);
#pragma unroll
        for (int kk = 0; kk < 16; kk++) {
            float a[8], b[8];
            float4 t;
            t = *(const float4*)&As[cur][kk][ty * 8];     a[0]=t.x;a[1]=t.y;a[2]=t.z;a[3]=t.w;
            t = *(const float4*)&As[cur][kk][ty * 8 + 4]; a[4]=t.x;a[5]=t.y;a[6]=t.z;a[7]=t.w;
            t = *(const float4*)&Bs[cur][kk][tx * 8];     b[0]=t.x;b[1]=t.y;b[2]=t.z;b[3]=t.w;
            t = *(const float4*)&Bs[cur][kk][tx * 8 + 4]; b[4]=t.x;b[5]=t.y;b[6]=t.z;b[7]=t.w;
#pragma unroll
            for (int i = 0; i < 8; i++)
#pragma unroll
                for (int j = 0; j < 8; j++) acc[i][j] += a[i] * b[j];
        }
        if (kt + 1 < nk) { STOREB(cur ^ 1); __syncthreads(); }
    }
#undef LOADG
#undef STOREB
    const float scale = 0.08838834764831845f;
#pragma unroll
    for (int i = 0; i < 8; i++) {
        int q = qbase + ty * 8 + i;
        float* srow = g_s + ((size_t)h * T_ + q) * T_ + kbase + tx * 8;
        int k0 = kbase + tx * 8;
        float v[8];
#pragma unroll
        for (int j = 0; j < 8; j++) v[j] = (k0 + j <= q) ? acc[i][j] * scale : -1e30f;
        *(float4*)srow = make_float4(v[0], v[1], v[2], v[3]);
        *(float4*)(srow + 4) = make_float4(v[4], v[5], v[6], v[7]);
    }
}

// ---------------- attention pass B: row softmax ----------------
__global__ __launch_bounds__(256)
void softmax_rows() {
    int q = blockIdx.x, h = blockIdx.y;
    float* row = g_s + ((size_t)h * T_ + q) * T_;
    int L = q + 1, pad_end = ((q >> 7) + 1) << 7, tid = threadIdx.x;
    float v[8];
    int nchunk = (L + 255) >> 8;
    float mx = -1e30f;
#pragma unroll 4
    for (int c = 0; c < nchunk; c++) {
        int i = c * 256 + tid;
        v[c] = (i < L) ? row[i] : -1e30f;
        mx = fmaxf(mx, v[c]);
    }
    mx = block_reduce_max(mx);
    float s = 0.f;
#pragma unroll 4
    for (int c = 0; c < nchunk; c++) { v[c] = __expf(v[c] - mx); s += v[c]; }
    float tot = block_reduce_sum(s);
    float inv = 1.f / tot;
#pragma unroll 4
    for (int c = 0; c < nchunk; c++) {
        int i = c * 256 + tid;
        if (i < L) row[i] = v[c] * inv;
    }
    for (int i = L + tid; i < pad_end; i += 256) row[i] = 0.f;
}

// ---------------- attention pass C: O = P @ V ----------------
__global__ __launch_bounds__(256, 2)
void gemm_pv() {
    int qt = (int)gridDim.x - 1 - (int)blockIdx.x;
    int h = blockIdx.y;
    int rbase = qt * 128, kvh = h >> 2;
    const float* Ap = g_s + (size_t)h * T_ * T_;
    const float* Bp = g_qkv + 2560 + kvh * DH_;
    __shared__ float As[2][16][132];
    __shared__ float Bs[2][16][132];
    int tid = threadIdx.x, tx = tid & 15, ty = tid >> 4;
    int am = tid & 127, ak0 = (tid >> 7) * 8;
    const float* Arow = Ap + (size_t)(rbase + am) * T_;
    int br0 = tid >> 5, bc4 = tid & 31;
    float acc[8][8];
#pragma unroll
    for (int i = 0; i < 8; i++)
#pragma unroll
        for (int j = 0; j < 8; j++) acc[i][j] = 0.f;
    float4 ra0, ra1, rb0, rb1;
#define LOADG(K0) do { ra0 = *(const float4*)(Arow + (K0) + ak0);                    \
        ra1 = *(const float4*)(Arow + (K0) + ak0 + 4);                               \
        rb0 = *(const float4*)(Bp + (size_t)((K0) + br0) * 3072 + bc4 * 4);          \
        rb1 = *(const float4*)(Bp + (size_t)((K0) + br0 + 8) * 3072 + bc4 * 4); } while (0)
#define STOREB(BUF) do {                                                             \
        As[BUF][ak0 + 0][am] = ra0.x; As[BUF][ak0 + 1][am] = ra0.y;                  \
        As[BUF][ak0 + 2][am] = ra0.z; As[BUF][ak0 + 3][am] = ra0.w;                  \
        As[BUF][ak0 + 4][am] = ra1.x; As[BUF][ak0 + 5][am] = ra1.y;                  \
        As[BUF][ak0 + 6][am] = ra1.z; As[BUF][ak0 + 7][am] = ra1.w;                  \
        *(float4*)&Bs[BUF][br0][bc4 * 4] = rb0;                                      \
        *(float4*)&Bs[BUF][br0 + 8][bc4 * 4] = rb1; } while (0)
    int nk = (qt + 1) * 8;
    LOADG(0); STOREB(0); __syncthreads();
    for (int kt = 0; kt < nk; kt++) {
        int cur = kt & 1;
        if (kt + 1 < nk) LOADG((kt + 1) * 16);
#pragma unroll
        for (int kk = 0; kk < 16; kk++) {
            float a[8], b[8];
            float4 t;
            t = *(const float4*)&As[cur][kk][ty * 8];     a[0]=t.x;a[1]=t.y;a[2]=t.z;a[3]=t.w;
            t = *(const float4*)&As[cur][kk][ty * 8 + 4]; a[4]=t.x;a[5]=t.y;a[6]=t.z;a[7]=t.w;
            t = *(const float4*)&Bs[cur][kk][tx * 8];     b[0]=t.x;b[1]=t.y;b[2]=t.z;b[3]=t.w;
            t = *(const float4*)&Bs[cur][kk][tx * 8 + 4]; b[4]=t.x;b[5]=t.y;b[6]=t.z;b[7]=t.w;
#pragma unroll
            for (int i = 0; i < 8; i++)
#pragma unroll
                for (int j = 0; j < 8; j++) acc[i][j] += a[i] * b[j];
        }
        if (kt + 1 < nk) { STOREB(cur ^ 1); __syncthreads(); }
    }
#undef LOADG
#undef STOREB
#pragma unroll
    for (int i = 0; i < 8; i++) {
        int q = rbase + ty * 8 + i;
        float* dst = g_attn + (size_t)q * (NH_ * DH_) + h * DH_ + tx * 8;
        *(float4*)dst = make_float4(acc[i][0], acc[i][1], acc[i][2], acc[i][3]);
        *(float4*)(dst + 4) = make_float4(acc[i][4], acc[i][5], acc[i][6], acc[i][7]);
    }
}

// ---------------- elementwise ----------------
__global__ void embcat_kernel(const int* __restrict__ ids,
                              const float* __restrict__ emb_w,
                              const float* __restrict__ hid,
                              const float* __restrict__ we,
                              const float* __restrict__ wh) {
    int t = blockIdx.x;
    const float* er = emb_w + (size_t)ids[t] * H_;
    const float* hr = hid + (size_t)t * H_;
    float ss = 0.f;
    for (int h = threadIdx.x; h < H_; h += blockDim.x) { float v = er[h]; ss += v * v; }
    float rs = rsqrtf(block_reduce_sum(ss) / H_ + EPS_);
    for (int h = threadIdx.x; h < H_; h += blockDim.x)
        g_cat[(size_t)t * 2 * H_ + h] = er[h] * rs * (1.f + we[h]);
    ss = 0.f;
    for (int h = threadIdx.x; h < H_; h += blockDim.x) { float v = hr[h]; ss += v * v; }
    rs = rsqrtf(block_reduce_sum(ss) / H_ + EPS_);
    for (int h = threadIdx.x; h < H_; h += blockDim.x)
        g_cat[(size_t)t * 2 * H_ + H_ + h] = hr[h] * rs * (1.f + wh[h]);
}

__global__ void rmsnorm_kernel(const float* __restrict__ in,
                               const float* __restrict__ w,
                               float* __restrict__ out) {
    int t = blockIdx.x;
    const float* r = in + (size_t)t * H_;
    float ss = 0.f;
    for (int h = threadIdx.x; h < H_; h += blockDim.x) { float v = r[h]; ss += v * v; }
    float rs = rsqrtf(block_reduce_sum(ss) / H_ + EPS_);
    for (int h = threadIdx.x; h < H_; h += blockDim.x)
        out[(size_t)t * H_ + h] = r[h] * rs * (1.f + w[h]);
}

__global__ void qkrope_kernel(int coloff, int nheads,
                              const float* __restrict__ nw,
                              const int* __restrict__ positions) {
    int t = blockIdx.x, h = blockIdx.y;
    float* v = g_qkv + (size_t)t * 3072 + coloff + h * DH_;
    int d = threadIdx.x;
    float val = v[d];
    float ss = val * val;
#pragma unroll
    for (int o = 16; o > 0; o >>= 1) ss += __shfl_xor_sync(0xffffffffu, ss, o);
    __shared__ float ws[4];
    if ((d & 31) == 0) ws[d >> 5] = ss;
    __syncthreads();
    float rs = rsqrtf((ws[0] + ws[1] + ws[2] + ws[3]) / DH_ + EPS_);
    float n = val * rs * (1.f + nw[d]);
    __shared__ float nv[DH_];
    nv[d] = n;
    __syncthreads();
    int pos = positions[t];
    int i = d & 63;
    float inv = expf(-((float)i / 64.f) * 13.815510557964274f);
    float ang = (float)pos * inv;
    float c = cosf(ang), s = sinf(ang);
    v[d] = (d < 64) ? nv[d] * c - nv[d + 64] * s : nv[d] * c + nv[d - 64] * s;
}

__global__ void zero_counts_kernel() { if (threadIdx.x < E_) g_counts[threadIdx.x] = 0; }

__global__ void router_kernel(const float* __restrict__ rw) {
    int t = blockIdx.x;
    __shared__ float part[256];
    __shared__ float logits[E_];
    int tid = threadIdx.x, e = tid >> 4, c = tid & 15;
    float s = 0.f;
    const float* xr = g_xn + (size_t)t * H_;
    for (int h = c * 128; h < (c + 1) * 128; h++) s += xr[h] * rw[(size_t)h * E_ + e];
    part[tid] = s;
    __syncthreads();
    if (c == 0) {
        float tot = 0.f;
        for (int i = 0; i < 16; i++) tot += part[e * 16 + i];
        logits[e] = tot;
    }
    __syncthreads();
    if (tid == 0) {
        float mx = -1e30f;
        for (int i = 0; i < E_; i++) mx = fmaxf(mx, logits[i]);
        float p[E_];
        for (int i = 0; i < E_; i++) p[i] = expf(logits[i] - mx);
        int i0 = 0; float v0 = p[0];
        for (int i = 1; i < E_; i++) if (p[i] > v0) { v0 = p[i]; i0 = i; }
        int i1 = -1; float v1 = -1.f;
        for (int i = 0; i < E_; i++) if (i != i0 && p[i] > v1) { v1 = p[i]; i1 = i; }
        float denom = v0 + v1;
        g_top_idx[t * 2 + 0] = i0; g_top_idx[t * 2 + 1] = i1;
        g_top_w[t * 2 + 0] = v0 / denom; g_top_w[t * 2 + 1] = v1 / denom;
        atomicAdd(&g_counts[i0], 1);
        atomicAdd(&g_counts[i1], 1);
    }
}

__global__ void offsets_kernel() {
    if (threadIdx.x == 0) {
        int acc = 0;
        for (int e = 0; e < E_; e++) { g_offs[e] = acc; acc += g_counts[e]; }
        g_offs[E_] = acc;
    }
    if (threadIdx.x < E_) g_counts2[threadIdx.x] = 0;
}

__global__ void scatter_kernel() {
    int t = blockIdx.x * blockDim.x + threadIdx.x;
    if (t >= T_) return;
    for (int k = 0; k < TOPK_; k++) {
        int e = g_top_idx[t * 2 + k];
        int pos = atomicAdd(&g_counts2[e], 1);
        int slot = g_offs[e] + pos;
        g_tok_of_slot[slot] = t;
        g_gate_of_slot[slot] = g_top_w[t * 2 + k];
        g_slot_of_tok[t * 2 + k] = slot;
    }
}

__global__ void silu_mul_kernel() {
    size_t i = (size_t)blockIdx.x * blockDim.x + threadIdx.x;
    if (i >= (size_t)T_ * TOPK_ * I_) return;
    float x = g_gbuf[i];
    g_gbuf[i] = (x / (1.f + expf(-x))) * g_ubuf[i];
}

__global__ void final_kernel(const float* __restrict__ fw, float* __restrict__ out) {
    int t = blockIdx.x;
    __shared__ float buf[H_];
    int s0 = g_slot_of_tok[t * 2 + 0], s1 = g_slot_of_tok[t * 2 + 1];
    float ss = 0.f;
    for (int h = threadIdx.x; h < H_; h += blockDim.x) {
        float v = g_x[(size_t)t * H_ + h] + g_downbuf[(size_t)s0 * H_ + h] +
                  g_downbuf[(size_t)s1 * H_ + h];
        buf[h] = v;
        ss += v * v;
    }
    float rs = rsqrtf(block_reduce_sum(ss) / H_ + EPS_);
    for (int h = threadIdx.x; h < H_; h += blockDim.x)
        out[(size_t)t * H_ + h] = buf[h] * rs * (1.f + fw[h]);
}

// ---------------- launch ----------------
extern "C" void kernel_launch(void* const* d_in, const int* in_sizes, int n_in,
                              void* d_out, int out_size) {
    const int* input_ids      = (const int*)d_in[0];
    const int* positions      = (const int*)d_in[1];
    const float* hidden       = (const float*)d_in[2];
    const float* embed_w      = (const float*)d_in[4];
    const float* fc_w         = (const float*)d_in[5];
    const float* pre_fc_emb_w = (const float*)d_in[6];
    const float* pre_fc_hid_w = (const float*)d_in[7];
    const float* in_ln_w      = (const float*)d_in[8];
    const float* post_ln_w    = (const float*)d_in[9];
    const float* final_norm_w = (const float*)d_in[10];
    const float* wq           = (const float*)d_in[11];
    const float* wk           = (const float*)d_in[12];
    const float* wv           = (const float*)d_in[13];
    const float* wo           = (const float*)d_in[14];
    const float* q_norm_w     = (const float*)d_in[15];
    const float* k_norm_w     = (const float*)d_in[16];
    const float* router_w     = (const float*)d_in[17];
    const float* w_gate       = (const float*)d_in[18];
    const float* w_up         = (const float*)d_in[19];
    const float* w_down       = (const float*)d_in[20];
    float* out = (float*)d_out;

    float *p_cat, *p_x, *p_res, *p_xn, *p_attn, *p_g, *p_u, *p_down, *p_gate;
    int *p_tok, *p_offs;
    cudaGetSymbolAddress((void**)&p_cat, g_cat);
    cudaGetSymbolAddress((void**)&p_x, g_x);
    cudaGetSymbolAddress((void**)&p_res, g_res);
    cudaGetSymbolAddress((void**)&p_xn, g_xn);
    cudaGetSymbolAddress((void**)&p_attn, g_attn);
    cudaGetSymbolAddress((void**)&p_g, g_gbuf);
    cudaGetSymbolAddress((void**)&p_u, g_ubuf);
    cudaGetSymbolAddress((void**)&p_down, g_downbuf);
    cudaGetSymbolAddress((void**)&p_gate, g_gate_of_slot);
    cudaGetSymbolAddress((void**)&p_tok, g_tok_of_slot);
    cudaGetSymbolAddress((void**)&p_offs, g_offs);

    // 1. embed + rms -> concat
    embcat_kernel<<<T_, 256>>>(input_ids, embed_w, hidden, pre_fc_emb_w, pre_fc_hid_w);

    // 2. fc (3xTF32 mma): x = cat @ fc_w ; residual = x
    gemm_t32<<<dim3(H_ / 128, T_ / 128), 256>>>(p_cat, fc_w, p_x, T_, 2 * H_,
                                                2 * H_, H_, H_, nullptr, nullptr, p_res,
                                                nullptr, 0, nullptr);

    // 3. in_ln
    rmsnorm_kernel<<<T_, 256>>>(p_x, in_ln_w, p_xn);

    // 4. fused qkv (3xTF32 mma)
    gemm_t32_qkv<<<dim3(24, T_ / 128), 256>>>(p_xn, wq, wk, wv);

    // 5. q/k norm + rope
    qkrope_kernel<<<dim3(T_, NH_), DH_>>>(0, NH_, q_norm_w, positions);
    qkrope_kernel<<<dim3(T_, NKV_), DH_>>>(2048, NKV_, k_norm_w, positions);

    // 6. attention (fp32): QK^T -> softmax -> PV
    gemm_qk<<<dim3(T_ / 128, T_ / 128, NH_), 256>>>();
    softmax_rows<<<dim3(T_, NH_), 256>>>();
    gemm_pv<<<dim3(T_ / 128, NH_), 256>>>();

    // 7. wo + residual (3xTF32 mma)
    gemm_t32<<<dim3(H_ / 128, T_ / 128), 256>>>(p_attn, wo, p_x, T_, NH_ * DH_,
                                                NH_ * DH_, H_, H_, nullptr, p_res, nullptr,
                                                nullptr, 0, nullptr);

    // 8. post_ln
    rmsnorm_kernel<<<T_, 256>>>(p_x, post_ln_w, p_xn);

    // 9. router + bucketing
    zero_counts_kernel<<<1, 32>>>();
    router_kernel<<<T_, 256>>>(router_w);
    offsets_kernel<<<1, 32>>>();
    scatter_kernel<<<(T_ + 255) / 256, 256>>>();

    // 10. MoE grouped GEMMs (3xTF32 mma)
    gemm_t32<<<dim3(I_ / 128, T_ / 128, E_), 256>>>(p_xn, w_gate, p_g, 0, H_,
                                                    H_, I_, I_, p_tok, nullptr, nullptr,
                                                    p_offs, (long long)H_ * I_, nullptr);
    gemm_t32<<<dim3(I_ / 128, T_ / 128, E_), 256>>>(p_xn, w_up, p_u, 0, H_,
                                                    H_, I_, I_, p_tok, nullptr, nullptr,
                                                    p_offs, (long long)H_ * I_, nullptr);
    silu_mul_kernel<<<((size_t)T_ * TOPK_ * I_ + 255) / 256, 256>>>();
    gemm_t32<<<dim3(H_ / 128, T_ / 128, E_), 256>>>(p_g, w_down, p_down, 0, I_,
                                                    I_, H_, H_, nullptr, nullptr, nullptr,
                                                    p_offs, (long long)I_ * H_, p_gate);

    // 11. combine + final rms
    final_kernel<<<T_, 256>>>(final_norm_w, out);
}

// round 13
// speedup vs baseline: 1.3695x; 1.0143x over previous
#include <cuda_runtime.h>
#include <math.h>
#include <stdint.h>

#define T_ 2048
#define H_ 2048
#define NH_ 16
#define NKV_ 4
#define DH_ 128
#define E_ 16
#define TOPK_ 2
#define I_ 1024
#define EPS_ 1e-6f

// ---------------- scratch ----------------
__device__ float g_cat[(size_t)T_ * 2 * H_];
__device__ float g_x[(size_t)T_ * H_];
__device__ float g_res[(size_t)T_ * H_];
__device__ float g_xn[(size_t)T_ * H_];
__device__ float g_qkv[(size_t)T_ * 3072];
__device__ float g_attn[(size_t)T_ * NH_ * DH_];
__device__ float g_s[(size_t)NH_ * T_ * T_];
__device__ float g_gbuf[(size_t)T_ * TOPK_ * I_];
__device__ float g_ubuf[(size_t)T_ * TOPK_ * I_];
__device__ float g_downbuf[(size_t)T_ * TOPK_ * H_];
__device__ int   g_top_idx[T_ * TOPK_];
__device__ float g_top_w[T_ * TOPK_];
__device__ int   g_counts[E_];
__device__ int   g_counts2[E_];
__device__ int   g_offs[E_ + 1];
__device__ int   g_tok_of_slot[T_ * TOPK_];
__device__ float g_gate_of_slot[T_ * TOPK_];
__device__ int   g_slot_of_tok[T_ * TOPK_];

// ---------------- helpers ----------------
__device__ __forceinline__ float block_reduce_sum(float v) {
    __shared__ float sb[33];
    int tid = threadIdx.x;
#pragma unroll
    for (int o = 16; o > 0; o >>= 1) v += __shfl_xor_sync(0xffffffffu, v, o);
    if ((tid & 31) == 0) sb[tid >> 5] = v;
    __syncthreads();
    if (tid == 0) {
        float s = 0.f;
        int nw = (blockDim.x + 31) >> 5;
        for (int i = 0; i < nw; i++) s += sb[i];
        sb[32] = s;
    }
    __syncthreads();
    return sb[32];
}
__device__ __forceinline__ float block_reduce_max(float v) {
    __shared__ float sb[33];
    int tid = threadIdx.x;
#pragma unroll
    for (int o = 16; o > 0; o >>= 1) v = fmaxf(v, __shfl_xor_sync(0xffffffffu, v, o));
    if ((tid & 31) == 0) sb[tid >> 5] = v;
    __syncthreads();
    if (tid == 0) {
        float s = -1e30f;
        int nw = (blockDim.x + 31) >> 5;
        for (int i = 0; i < nw; i++) s = fmaxf(s, sb[i]);
        sb[32] = s;
    }
    __syncthreads();
    return sb[32];
}

__device__ __forceinline__ void t32split(float x, uint32_t& h, uint32_t& l) {
    uint32_t hb;
    asm("cvt.rna.tf32.f32 %0, %1;" : "=r"(hb) : "f"(x));
    float hf = __uint_as_float(hb);
    asm("cvt.rna.tf32.f32 %0, %1;" : "=r"(l) : "f"(x - hf));
    h = hb;
}
__device__ __forceinline__ void mma_tf32(float* d, const uint32_t* a, const uint32_t* b) {
    asm volatile("mma.sync.aligned.m16n8k8.row.col.f32.tf32.tf32.f32 "
                 "{%0,%1,%2,%3}, {%4,%5,%6,%7}, {%8,%9}, {%0,%1,%2,%3};"
                 : "+f"(d[0]), "+f"(d[1]), "+f"(d[2]), "+f"(d[3])
                 : "r"(a[0]), "r"(a[1]), "r"(a[2]), "r"(a[3]), "r"(b[0]), "r"(b[1]));
}

#define TP 136   // smem pitch (words); 136 % 32 = 8 -> all frag loads conflict-free

// ---------------- 3xTF32 tensor GEMM skeleton: 128x128 tile, 8 warps (4m x 2n) ----------------
#define T32_DECL()                                                                   \
    __shared__ float As[2][16 * TP];                                                 \
    __shared__ float Bs[2][16 * TP];                                                 \
    int tid = threadIdx.x, lane = tid & 31, wid = tid >> 5;                          \
    int m0 = (wid & 3) * 32, n0 = (wid >> 2) * 64;                                   \
    int fr = lane >> 2, kc = lane & 3;                                               \
    int am = tid & 127, ak0 = (tid >> 7) * 8;                                        \
    float acc[2][8][4];                                                              \
    _Pragma("unroll") for (int i_ = 0; i_ < 2; i_++)                                 \
        _Pragma("unroll") for (int j_ = 0; j_ < 8; j_++)                             \
            _Pragma("unroll") for (int c_ = 0; c_ < 4; c_++) acc[i_][j_][c_] = 0.f;  \
    float4 ra0, ra1, rb0, rb1;                                                       \
    const float4 Z4 = make_float4(0.f, 0.f, 0.f, 0.f);                               \
    (void)Z4;

#define T32_STORE_A_TR(BUF)                                                          \
    do {                                                                             \
        As[BUF][(ak0 + 0) * TP + am] = ra0.x;                                        \
        As[BUF][(ak0 + 1) * TP + am] = ra0.y;                                        \
        As[BUF][(ak0 + 2) * TP + am] = ra0.z;                                        \
        As[BUF][(ak0 + 3) * TP + am] = ra0.w;                                        \
        As[BUF][(ak0 + 4) * TP + am] = ra1.x;                                        \
        As[BUF][(ak0 + 5) * TP + am] = ra1.y;                                        \
        As[BUF][(ak0 + 6) * TP + am] = ra1.z;                                        \
        As[BUF][(ak0 + 7) * TP + am] = ra1.w;                                        \
    } while (0)

#define T32_STORE_B_TR(BUF)                                                          \
    do {                                                                             \
        Bs[BUF][(ak0 + 0) * TP + am] = rb0.x;                                        \
        Bs[BUF][(ak0 + 1) * TP + am] = rb0.y;                                        \
        Bs[BUF][(ak0 + 2) * TP + am] = rb0.z;                                        \
        Bs[BUF][(ak0 + 3) * TP + am] = rb0.w;                                        \
        Bs[BUF][(ak0 + 4) * TP + am] = rb1.x;                                        \
        Bs[BUF][(ak0 + 5) * TP + am] = rb1.y;                                        \
        Bs[BUF][(ak0 + 6) * TP + am] = rb1.z;                                        \
        Bs[BUF][(ak0 + 7) * TP + am] = rb1.w;                                        \
    } while (0)

#define T32_STORE_B_ROW(BUF, BR0, BC4)                                               \
    do {                                                                             \
        *(float4*)&Bs[BUF][(BR0) * TP + (BC4) * 4] = rb0;                            \
        *(float4*)&Bs[BUF][((BR0) + 8) * TP + (BC4) * 4] = rb1;                      \
    } while (0)

#define T32_COMPUTE(CUR)                                                             \
    _Pragma("unroll")                                                                \
    for (int s = 0; s < 2; s++) {                                                    \
        const float* Ab  = &As[CUR][(s * 8 + kc) * TP];                              \
        const float* Ab4 = &As[CUR][(s * 8 + kc + 4) * TP];                          \
        const float* Bb  = &Bs[CUR][(s * 8 + kc) * TP];                              \
        const float* Bb4 = &Bs[CUR][(s * 8 + kc + 4) * TP];                          \
        uint32_t ah[2][4], al[2][4], bh[8][2], bl[8][2];                             \
        _Pragma("unroll")                                                            \
        for (int mt = 0; mt < 2; mt++) {                                             \
            int mm = m0 + mt * 16 + fr;                                              \
            t32split(Ab[mm],      ah[mt][0], al[mt][0]);                             \
            t32split(Ab[mm + 8],  ah[mt][1], al[mt][1]);                             \
            t32split(Ab4[mm],     ah[mt][2], al[mt][2]);                             \
            t32split(Ab4[mm + 8], ah[mt][3], al[mt][3]);                             \
        }                                                                            \
        _Pragma("unroll")                                                            \
        for (int nt = 0; nt < 8; nt++) {                                             \
            int nn = n0 + nt * 8 + fr;                                               \
            t32split(Bb[nn],  bh[nt][0], bl[nt][0]);                                 \
            t32split(Bb4[nn], bh[nt][1], bl[nt][1]);                                 \
        }                                                                            \
        _Pragma("unroll")                                                            \
        for (int mt = 0; mt < 2; mt++)                                               \
            _Pragma("unroll")                                                        \
            for (int nt = 0; nt < 8; nt++) {                                         \
                mma_tf32(acc[mt][nt], ah[mt], bh[nt]);                               \
                mma_tf32(acc[mt][nt], ah[mt], bl[nt]);                               \
                mma_tf32(acc[mt][nt], al[mt], bh[nt]);                               \
            }                                                                        \
    }

// ---------------- generic weight GEMM (A row-major gather, B row-major) ----------------
__global__ __launch_bounds__(256, 2)
void gemm_t32(const float* __restrict__ A, const float* __restrict__ B,
              float* __restrict__ C,
              int M, int Kd, int lda, int ldb, int ldc,
              const int* __restrict__ rowmap,
              const float* __restrict__ addsrc, float* __restrict__ Cdup,
              const int* __restrict__ segoff, long long strideB,
              const float* __restrict__ rowscale) {
    int row0 = 0, rowEnd = M;
    const float* Bp = B;
    if (segoff) {
        int e = blockIdx.z;
        row0 = segoff[e];
        rowEnd = segoff[e + 1];
        Bp = B + (long long)e * strideB;
    }
    int rbase = row0 + blockIdx.y * 128;
    if (rbase >= rowEnd) return;
    int cbase = blockIdx.x * 128;

    T32_DECL();
    const float* Arow = nullptr;
    if (rbase + am < rowEnd) {
        int m = rowmap ? rowmap[rbase + am] : rbase + am;
        Arow = A + (long long)m * lda;
    }
    const float* Brow_ = Bp + cbase;
    int br0 = tid >> 5, bc4 = tid & 31;

#define LOADG(K0)                                                                    \
    do {                                                                             \
        if (Arow) {                                                                  \
            ra0 = *(const float4*)(Arow + (K0) + ak0);                               \
            ra1 = *(const float4*)(Arow + (K0) + ak0 + 4);                           \
        } else { ra0 = Z4; ra1 = Z4; }                                               \
        rb0 = *(const float4*)(Brow_ + (long long)((K0) + br0) * ldb + bc4 * 4);     \
        rb1 = *(const float4*)(Brow_ + (long long)((K0) + br0 + 8) * ldb + bc4 * 4); \
    } while (0)

    int nk = Kd >> 4;
    LOADG(0);
    T32_STORE_A_TR(0);
    T32_STORE_B_ROW(0, br0, bc4);
    __syncthreads();
    for (int kt = 0; kt < nk; kt++) {
        int cur = kt & 1;
        if (kt + 1 < nk) LOADG((kt + 1) * 16);
        T32_COMPUTE(cur);
        if (kt + 1 < nk) {
            T32_STORE_A_TR(cur ^ 1);
            T32_STORE_B_ROW(cur ^ 1, br0, bc4);
            __syncthreads();
        }
    }
#undef LOADG

#pragma unroll
    for (int mt = 0; mt < 2; mt++)
#pragma unroll
        for (int half = 0; half < 2; half++) {
            int row = rbase + m0 + mt * 16 + fr + half * 8;
            if (row >= rowEnd) continue;
            float sc = rowscale ? rowscale[row] : 1.f;
            long long base = (long long)row * ldc + cbase + n0 + 2 * kc;
#pragma unroll
            for (int nt = 0; nt < 8; nt++) {
                long long o = base + nt * 8;
                float2 v = make_float2(acc[mt][nt][half * 2 + 0] * sc,
                                       acc[mt][nt][half * 2 + 1] * sc);
                if (addsrc) {
                    float2 s = *(const float2*)(addsrc + o);
                    v.x += s.x; v.y += s.y;
                }
                *(float2*)(C + o) = v;
                if (Cdup) *(float2*)(Cdup + o) = v;
            }
        }
}

// fused QKV variant -> g_qkv[T][3072]
__global__ __launch_bounds__(256, 2)
void gemm_t32_qkv(const float* __restrict__ A,
                  const float* __restrict__ wq, const float* __restrict__ wk,
                  const float* __restrict__ wv) {
    int x = blockIdx.x;
    const float* Bsel;
    int ldb, bcol;
    if (x < 16)      { Bsel = wq; ldb = 2048; bcol = x * 128; }
    else if (x < 20) { Bsel = wk; ldb = 512;  bcol = (x - 16) * 128; }
    else             { Bsel = wv; ldb = 512;  bcol = (x - 20) * 128; }
    int ccol = x * 128;
    int rbase = blockIdx.y * 128;

    T32_DECL();
    const float* Arow = A + (long long)(rbase + am) * H_;
    const float* Brow_ = Bsel + bcol;
    int br0 = tid >> 5, bc4 = tid & 31;

#define LOADG(K0)                                                                    \
    do {                                                                             \
        ra0 = *(const float4*)(Arow + (K0) + ak0);                                   \
        ra1 = *(const float4*)(Arow + (K0) + ak0 + 4);                               \
        rb0 = *(const float4*)(Brow_ + (long long)((K0) + br0) * ldb + bc4 * 4);     \
        rb1 = *(const float4*)(Brow_ + (long long)((K0) + br0 + 8) * ldb + bc4 * 4); \
    } while (0)

    int nk = H_ >> 4;
    LOADG(0);
    T32_STORE_A_TR(0);
    T32_STORE_B_ROW(0, br0, bc4);
    __syncthreads();
    for (int kt = 0; kt < nk; kt++) {
        int cur = kt & 1;
        if (kt + 1 < nk) LOADG((kt + 1) * 16);
        T32_COMPUTE(cur);
        if (kt + 1 < nk) {
            T32_STORE_A_TR(cur ^ 1);
            T32_STORE_B_ROW(cur ^ 1, br0, bc4);
            __syncthreads();
        }
    }
#undef LOADG

#pragma unroll
    for (int mt = 0; mt < 2; mt++)
#pragma unroll
        for (int half = 0; half < 2; half++) {
            int row = rbase + m0 + mt * 16 + fr + half * 8;
            long long base = (long long)row * 3072 + ccol + n0 + 2 * kc;
#pragma unroll
            for (int nt = 0; nt < 8; nt++)
                *(float2*)(g_qkv + base + nt * 8) =
                    make_float2(acc[mt][nt][half * 2 + 0], acc[mt][nt][half * 2 + 1]);
        }
}

// ---------------- attention pass A (3xTF32): S = scale*Q@K^T, causal tiles ----------------
__global__ __launch_bounds__(256, 2)
void gemm_t32_qk() {
    int ktile = blockIdx.x, qtile = blockIdx.y, h = blockIdx.z;
    if (ktile > qtile) return;
    int qbase = qtile * 128, kbase = ktile * 128, kvh = h >> 2;

    T32_DECL();
    const float* Arow = g_qkv + (size_t)(qbase + am) * 3072 + h * DH_;
    const float* Brow = g_qkv + (size_t)(kbase + am) * 3072 + 2048 + kvh * DH_;

#define LOADG(K0)                                                                    \
    do {                                                                             \
        ra0 = *(const float4*)(Arow + (K0) + ak0);                                   \
        ra1 = *(const float4*)(Arow + (K0) + ak0 + 4);                               \
        rb0 = *(const float4*)(Brow + (K0) + ak0);                                   \
        rb1 = *(const float4*)(Brow + (K0) + ak0 + 4);                               \
    } while (0)

    const int nk = DH_ >> 4;   // 8
    LOADG(0);
    T32_STORE_A_TR(0);
    T32_STORE_B_TR(0);
    __syncthreads();
    for (int kt = 0; kt < nk; kt++) {
        int cur = kt & 1;
        if (kt + 1 < nk) LOADG((kt + 1) * 16);
        T32_COMPUTE(cur);
        if (kt + 1 < nk) {
            T32_STORE_A_TR(cur ^ 1);
            T32_STORE_B_TR(cur ^ 1);
            __syncthreads();
        }
    }
#undef LOADG

    const float scale = 0.08838834764831845f;
#pragma unroll
    for (int mt = 0; mt < 2; mt++)
#pragma unroll
        for (int half = 0; half < 2; half++) {
            int q = qbase + m0 + mt * 16 + fr + half * 8;
            float* srow = g_s + ((size_t)h * T_ + q) * T_ + kbase + n0 + 2 * kc;
            int k0 = kbase + n0 + 2 * kc;
#pragma unroll
            for (int nt = 0; nt < 8; nt++) {
                float v0 = (k0 + nt * 8 + 0 <= q) ? acc[mt][nt][half * 2 + 0] * scale : -1e30f;
                float v1 = (k0 + nt * 8 + 1 <= q) ? acc[mt][nt][half * 2 + 1] * scale : -1e30f;
                *(float2*)(srow + nt * 8) = make_float2(v0, v1);
            }
        }
}

// ---------------- attention pass B: row softmax ----------------
__global__ __launch_bounds__(256)
void softmax_rows() {
    int q = blockIdx.x, h = blockIdx.y;
    float* row = g_s + ((size_t)h * T_ + q) * T_;
    int L = q + 1, pad_end = ((q >> 7) + 1) << 7, tid = threadIdx.x;
    float v[8];
    int nchunk = (L + 255) >> 8;
    float mx = -1e30f;
#pragma unroll 4
    for (int c = 0; c < nchunk; c++) {
        int i = c * 256 + tid;
        v[c] = (i < L) ? row[i] : -1e30f;
        mx = fmaxf(mx, v[c]);
    }
    mx = block_reduce_max(mx);
    float s = 0.f;
#pragma unroll 4
    for (int c = 0; c < nchunk; c++) { v[c] = __expf(v[c] - mx); s += v[c]; }
    float tot = block_reduce_sum(s);
    float inv = 1.f / tot;
#pragma unroll 4
    for (int c = 0; c < nchunk; c++) {
        int i = c * 256 + tid;
        if (i < L) row[i] = v[c] * inv;
    }
    for (int i = L + tid; i < pad_end; i += 256) row[i] = 0.f;
}

// ---------------- attention pass C (3xTF32): O = P @ V ----------------
__global__ __launch_bounds__(256, 2)
void gemm_t32_pv() {
    int qt = (int)gridDim.x - 1 - (int)blockIdx.x;   // longest first
    int h = blockIdx.y;
    int rbase = qt * 128, kvh = h >> 2;

    T32_DECL();
    const float* Arow = g_s + (size_t)h * T_ * T_ + (size_t)(rbase + am) * T_;
    const float* Bp = g_qkv + 2560 + kvh * DH_;     // V, row stride 3072
    int br0 = tid >> 5, bc4 = tid & 31;

#define LOADG(K0)                                                                    \
    do {                                                                             \
        ra0 = *(const float4*)(Arow + (K0) + ak0);                                   \
        ra1 = *(const float4*)(Arow + (K0) + ak0 + 4);                               \
        rb0 = *(const float4*)(Bp + (size_t)((K0) + br0) * 3072 + bc4 * 4);          \
        rb1 = *(const float4*)(Bp + (size_t)((K0) + br0 + 8) * 3072 + bc4 * 4);      \
    } while (0)

    int nk = (qt + 1) * 8;
    LOADG(0);
    T32_STORE_A_TR(0);
    T32_STORE_B_ROW(0, br0, bc4);
    __syncthreads();
    for (int kt = 0; kt < nk; kt++) {
        int cur = kt & 1;
        if (kt + 1 < nk) LOADG((kt + 1) * 16);
        T32_COMPUTE(cur);
        if (kt + 1 < nk) {
            T32_STORE_A_TR(cur ^ 1);
            T32_STORE_B_ROW(cur ^ 1, br0, bc4);
            __syncthreads();
        }
    }
#undef LOADG

#pragma unroll
    for (int mt = 0; mt < 2; mt++)
#pragma unroll
        for (int half = 0; half < 2; half++) {
            int q = rbase + m0 + mt * 16 + fr + half * 8;
            float* dst = g_attn + (size_t)q * (NH_ * DH_) + h * DH_ + n0 + 2 * kc;
#pragma unroll
            for (int nt = 0; nt < 8; nt++)
                *(float2*)(dst + nt * 8) =
                    make_float2(acc[mt][nt][half * 2 + 0], acc[mt][nt][half * 2 + 1]);
        }
}

// ---------------- elementwise ----------------
__global__ void embcat_kernel(const int* __restrict__ ids,
                              const float* __restrict__ emb_w,
                              const float* __restrict__ hid,
                              const float* __restrict__ we,
                              const float* __restrict__ wh) {
    int t = blockIdx.x;
    const float* er = emb_w + (size_t)ids[t] * H_;
    const float* hr = hid + (size_t)t * H_;
    float ss = 0.f;
    for (int h = threadIdx.x; h < H_; h += blockDim.x) { float v = er[h]; ss += v * v; }
    float rs = rsqrtf(block_reduce_sum(ss) / H_ + EPS_);
    for (int h = threadIdx.x; h < H_; h += blockDim.x)
        g_cat[(size_t)t * 2 * H_ + h] = er[h] * rs * (1.f + we[h]);
    ss = 0.f;
    for (int h = threadIdx.x; h < H_; h += blockDim.x) { float v = hr[h]; ss += v * v; }
    rs = rsqrtf(block_reduce_sum(ss) / H_ + EPS_);
    for (int h = threadIdx.x; h < H_; h += blockDim.x)
        g_cat[(size_t)t * 2 * H_ + H_ + h] = hr[h] * rs * (1.f + wh[h]);
}

__global__ void rmsnorm_kernel(const float* __restrict__ in,
                               const float* __restrict__ w,
                               float* __restrict__ out) {
    int t = blockIdx.x;
    const float* r = in + (size_t)t * H_;
    float ss = 0.f;
    for (int h = threadIdx.x; h < H_; h += blockDim.x) { float v = r[h]; ss += v * v; }
    float rs = rsqrtf(block_reduce_sum(ss) / H_ + EPS_);
    for (int h = threadIdx.x; h < H_; h += blockDim.x)
        out[(size_t)t * H_ + h] = r[h] * rs * (1.f + w[h]);
}

__global__ void qkrope_kernel(int coloff, int nheads,
                              const float* __restrict__ nw,
                              const int* __restrict__ positions) {
    int t = blockIdx.x, h = blockIdx.y;
    float* v = g_qkv + (size_t)t * 3072 + coloff + h * DH_;
    int d = threadIdx.x;
    float val = v[d];
    float ss = val * val;
#pragma unroll
    for (int o = 16; o > 0; o >>= 1) ss += __shfl_xor_sync(0xffffffffu, ss, o);
    __shared__ float ws[4];
    if ((d & 31) == 0) ws[d >> 5] = ss;
    __syncthreads();
    float rs = rsqrtf((ws[0] + ws[1] + ws[2] + ws[3]) / DH_ + EPS_);
    float n = val * rs * (1.f + nw[d]);
    __shared__ float nv[DH_];
    nv[d] = n;
    __syncthreads();
    int pos = positions[t];
    int i = d & 63;
    float inv = expf(-((float)i / 64.f) * 13.815510557964274f);
    float ang = (float)pos * inv;
    float c = cosf(ang), s = sinf(ang);
    v[d] = (d < 64) ? nv[d] * c - nv[d + 64] * s : nv[d] * c + nv[d - 64] * s;
}

__global__ void zero_counts_kernel() { if (threadIdx.x < E_) g_counts[threadIdx.x] = 0; }

__global__ void router_kernel(const float* __restrict__ rw) {
    int t = blockIdx.x;
    __shared__ float part[256];
    __shared__ float logits[E_];
    int tid = threadIdx.x, e = tid >> 4, c = tid & 15;
    float s = 0.f;
    const float* xr = g_xn + (size_t)t * H_;
    for (int h = c * 128; h < (c + 1) * 128; h++) s += xr[h] * rw[(size_t)h * E_ + e];
    part[tid] = s;
    __syncthreads();
    if (c == 0) {
        float tot = 0.f;
        for (int i = 0; i < 16; i++) tot += part[e * 16 + i];
        logits[e] = tot;
    }
    __syncthreads();
    if (tid == 0) {
        float mx = -1e30f;
        for (int i = 0; i < E_; i++) mx = fmaxf(mx, logits[i]);
        float p[E_];
        for (int i = 0; i < E_; i++) p[i] = expf(logits[i] - mx);
        int i0 = 0; float v0 = p[0];
        for (int i = 1; i < E_; i++) if (p[i] > v0) { v0 = p[i]; i0 = i; }
        int i1 = -1; float v1 = -1.f;
        for (int i = 0; i < E_; i++) if (i != i0 && p[i] > v1) { v1 = p[i]; i1 = i; }
        float denom = v0 + v1;
        g_top_idx[t * 2 + 0] = i0; g_top_idx[t * 2 + 1] = i1;
        g_top_w[t * 2 + 0] = v0 / denom; g_top_w[t * 2 + 1] = v1 / denom;
        atomicAdd(&g_counts[i0], 1);
        atomicAdd(&g_counts[i1], 1);
    }
}

__global__ void offsets_kernel() {
    if (threadIdx.x == 0) {
        int acc = 0;
        for (int e = 0; e < E_; e++) { g_offs[e] = acc; acc += g_counts[e]; }
        g_offs[E_] = acc;
    }
    if (threadIdx.x < E_) g_counts2[threadIdx.x] = 0;
}

__global__ void scatter_kernel() {
    int t = blockIdx.x * blockDim.x + threadIdx.x;
    if (t >= T_) return;
    for (int k = 0; k < TOPK_; k++) {
        int e = g_top_idx[t * 2 + k];
        int pos = atomicAdd(&g_counts2[e], 1);
        int slot = g_offs[e] + pos;
        g_tok_of_slot[slot] = t;
        g_gate_of_slot[slot] = g_top_w[t * 2 + k];
        g_slot_of_tok[t * 2 + k] = slot;
    }
}

__global__ void silu_mul_kernel() {
    size_t i = (size_t)blockIdx.x * blockDim.x + threadIdx.x;
    if (i >= (size_t)T_ * TOPK_ * I_) return;
    float x = g_gbuf[i];
    g_gbuf[i] = (x / (1.f + expf(-x))) * g_ubuf[i];
}

__global__ void final_kernel(const float* __restrict__ fw, float* __restrict__ out) {
    int t = blockIdx.x;
    __shared__ float buf[H_];
    int s0 = g_slot_of_tok[t * 2 + 0], s1 = g_slot_of_tok[t * 2 + 1];
    float ss = 0.f;
    for (int h = threadIdx.x; h < H_; h += blockDim.x) {
        float v = g_x[(size_t)t * H_ + h] + g_downbuf[(size_t)s0 * H_ + h] +
                  g_downbuf[(size_t)s1 * H_ + h];
        buf[h] = v;
        ss += v * v;
    }
    float rs = rsqrtf(block_reduce_sum(ss) / H_ + EPS_);
    for (int h = threadIdx.x; h < H_; h += blockDim.x)
        out[(size_t)t * H_ + h] = buf[h] * rs * (1.f + fw[h]);
}

// ---------------- launch ----------------
extern "C" void kernel_launch(void* const* d_in, const int* in_sizes, int n_in,
                              void* d_out, int out_size) {
    const int* input_ids      = (const int*)d_in[0];
    const int* positions      = (const int*)d_in[1];
    const float* hidden       = (const float*)d_in[2];
    const float* embed_w      = (const float*)d_in[4];
    const float* fc_w         = (const float*)d_in[5];
    const float* pre_fc_emb_w = (const float*)d_in[6];
    const float* pre_fc_hid_w = (const float*)d_in[7];
    const float* in_ln_w      = (const float*)d_in[8];
    const float* post_ln_w    = (const float*)d_in[9];
    const float* final_norm_w = (const float*)d_in[10];
    const float* wq           = (const float*)d_in[11];
    const float* wk           = (const float*)d_in[12];
    const float* wv           = (const float*)d_in[13];
    const float* wo           = (const float*)d_in[14];
    const float* q_norm_w     = (const float*)d_in[15];
    const float* k_norm_w     = (const float*)d_in[16];
    const float* router_w     = (const float*)d_in[17];
    const float* w_gate       = (const float*)d_in[18];
    const float* w_up         = (const float*)d_in[19];
    const float* w_down       = (const float*)d_in[20];
    float* out = (float*)d_out;

    float *p_cat, *p_x, *p_res, *p_xn, *p_attn, *p_g, *p_u, *p_down, *p_gate;
    int *p_tok, *p_offs;
    cudaGetSymbolAddress((void**)&p_cat, g_cat);
    cudaGetSymbolAddress((void**)&p_x, g_x);
    cudaGetSymbolAddress((void**)&p_res, g_res);
    cudaGetSymbolAddress((void**)&p_xn, g_xn);
    cudaGetSymbolAddress((void**)&p_attn, g_attn);
    cudaGetSymbolAddress((void**)&p_g, g_gbuf);
    cudaGetSymbolAddress((void**)&p_u, g_ubuf);
    cudaGetSymbolAddress((void**)&p_down, g_downbuf);
    cudaGetSymbolAddress((void**)&p_gate, g_gate_of_slot);
    cudaGetSymbolAddress((void**)&p_tok, g_tok_of_slot);
    cudaGetSymbolAddress((void**)&p_offs, g_offs);

    // 1. embed + rms -> concat
    embcat_kernel<<<T_, 256>>>(input_ids, embed_w, hidden, pre_fc_emb_w, pre_fc_hid_w);

    // 2. fc (3xTF32): x = cat @ fc_w ; residual = x
    gemm_t32<<<dim3(H_ / 128, T_ / 128), 256>>>(p_cat, fc_w, p_x, T_, 2 * H_,
                                                2 * H_, H_, H_, nullptr, nullptr, p_res,
                                                nullptr, 0, nullptr);

    // 3. in_ln
    rmsnorm_kernel<<<T_, 256>>>(p_x, in_ln_w, p_xn);

    // 4. fused qkv (3xTF32)
    gemm_t32_qkv<<<dim3(24, T_ / 128), 256>>>(p_xn, wq, wk, wv);

    // 5. q/k norm + rope
    qkrope_kernel<<<dim3(T_, NH_), DH_>>>(0, NH_, q_norm_w, positions);
    qkrope_kernel<<<dim3(T_, NKV_), DH_>>>(2048, NKV_, k_norm_w, positions);

    // 6. attention: QK^T (3xTF32) -> softmax (fp32) -> PV (3xTF32)
    gemm_t32_qk<<<dim3(T_ / 128, T_ / 128, NH_), 256>>>();
    softmax_rows<<<dim3(T_, NH_), 256>>>();
    gemm_t32_pv<<<dim3(T_ / 128, NH_), 256>>>();

    // 7. wo + residual (3xTF32)
    gemm_t32<<<dim3(H_ / 128, T_ / 128), 256>>>(p_attn, wo, p_x, T_, NH_ * DH_,
                                                NH_ * DH_, H_, H_, nullptr, p_res, nullptr,
                                                nullptr, 0, nullptr);

    // 8. post_ln
    rmsnorm_kernel<<<T_, 256>>>(p_x, post_ln_w, p_xn);

    // 9. router + bucketing
    zero_counts_kernel<<<1, 32>>>();
    router_kernel<<<T_, 256>>>(router_w);
    offsets_kernel<<<1, 32>>>();
    scatter_kernel<<<(T_ + 255) / 256, 256>>>();

    // 10. MoE grouped GEMMs (3xTF32)
    gemm_t32<<<dim3(I_ / 128, T_ / 128, E_), 256>>>(p_xn, w_gate, p_g, 0, H_,
                                                    H_, I_, I_, p_tok, nullptr, nullptr,
                                                    p_offs, (long long)H_ * I_, nullptr);
    gemm_t32<<<dim3(I_ / 128, T_ / 128, E_), 256>>>(p_xn, w_up, p_u, 0, H_,
                                                    H_, I_, I_, p_tok, nullptr, nullptr,
                                                    p_offs, (long long)H_ * I_, nullptr);
    silu_mul_kernel<<<((size_t)T_ * TOPK_ * I_ + 255) / 256, 256>>>();
    gemm_t32<<<dim3(H_ / 128, T_ / 128, E_), 256>>>(p_g, w_down, p_down, 0, I_,
                                                    I_, H_, H_, nullptr, nullptr, nullptr,
                                                    p_offs, (long long)I_ * H_, p_gate);

    // 11. combine + final rms
    final_kernel<<<T_, 256>>>(final_norm_w, out);
}